// round 9
// baseline (speedup 1.0000x reference)
#include <cuda_runtime.h>
#include <math.h>

#define Bn 16
#define Hn 512
#define Wn 512
#define C1 16
#define C2 18
#define TW 32          // K2 tile width
#define THY 16         // K2 tile height
#define HY 18          // THY+2 rows
#define W2R 40         // K2 smem row stride (floats)
#define CPLANE (HY*W2R)          // 720 floats per channel
#define NCHUNK (C1*HY*10)        // 2880 16B-chunks per block

typedef unsigned long long u64;

// 256 MB scratch for conv1 output (B, C1, H, W)
__device__ float g_feat[(size_t)Bn * C1 * Hn * Wn];
// duplicated conv1 weights, staged by prep kernel then copied to constant
__device__ float2 g_w1d[C1 * 27];

// constant memory (uniform access -> LDCU, no smem traffic)
__constant__ float2 c_w1d[C1 * 27];    // duplicated (w,w) pairs
__constant__ float  c_b1[C1];
__constant__ float  c_w2[C2 * C1 * 9];
__constant__ float  c_b2[C2];
__constant__ float  c_wk[9];

// ---- f32x2 packed helpers (sm_100+) --------------------------------------
__device__ __forceinline__ u64 pack2(float lo, float hi) {
    u64 r;
    asm("mov.b64 %0, {%1, %2};" : "=l"(r) : "f"(lo), "f"(hi));
    return r;
}
__device__ __forceinline__ void unpack2(u64 v, float& lo, float& hi) {
    asm("mov.b64 {%0, %1}, %2;" : "=f"(lo), "=f"(hi) : "l"(v));
}
__device__ __forceinline__ void fma2(u64& d, u64 a, u64 b) {
    asm("fma.rn.f32x2 %0, %1, %2, %0;" : "+l"(d) : "l"(a), "l"(b));
}

// ---- cp.async 16B with full-chunk zero-fill predication ------------------
__device__ __forceinline__ void cp_async16(unsigned smem_addr,
                                           const void* gptr, bool pred) {
    int sz = pred ? 16 : 0;
    asm volatile("cp.async.cg.shared.global [%0], [%1], 16, %2;"
                 :: "r"(smem_addr), "l"(gptr), "r"(sz) : "memory");
}

// ---- fast exact-enough GELU: Abramowitz-Stegun 7.1.26 erf, |err|<=1.5e-7 --
__device__ __forceinline__ float gelu_as(float a) {
    const float is2 = 0.70710678118654752440f;
    float z = a * is2;
    float s = fabsf(z);
    float t = __fdividef(1.0f, fmaf(0.3275911f, s, 1.0f));
    float e = __expf(-s * s);
    float poly = fmaf(fmaf(fmaf(fmaf(1.061405429f, t, -1.453152027f), t,
                              1.421413741f), t, -0.284496736f), t,
                      0.254829592f) * t;
    float er = fmaf(-poly, e, 1.0f);          // erf(|z|)
    er = (z < 0.0f) ? -er : er;
    float h = 0.5f * a;
    return fmaf(h, er, h);
}

// ---------------------------------------------------------------------------
// Prep kernel: duplicate conv1 weights into (w, w) float2 pairs.
// ---------------------------------------------------------------------------
__global__ void prep_weights_kernel(const float* __restrict__ w1) {
    int i = threadIdx.x;
    if (i < C1 * 27) {
        float v = w1[i];
        g_w1d[i] = make_float2(v, v);
    }
}

// ---------------------------------------------------------------------------
// Kernel 1: conv1 (3->16, 3x3, pad 1) + bias + exact GELU -> g_feat
// Horizontal pixel pair per thread. FFMA2 with LDCU.64 duplicated weights.
// ---------------------------------------------------------------------------
__global__ __launch_bounds__(256, 3) void conv1_gelu_kernel(
        const float* __restrict__ wind,
        const float* __restrict__ topo) {
    int tid = threadIdx.x;
    int idx = blockIdx.x * blockDim.x + tid;      // [0, B*H*(W/2))
    int xh = idx & 255;                           // W/2 = 256
    int x0 = xh << 1;                             // even column
    int r  = idx >> 8;
    int y  = r & (Hn - 1);
    int b  = r >> 9;

    const float* chp[3] = {
        wind + ((size_t)b * 2 + 0) * Hn * Wn,
        wind + ((size_t)b * 2 + 1) * Hn * Wn,
        topo + (size_t)b * Hn * Wn
    };

    // packed horizontal feature pairs p[c*9 + ky*3 + kx] for outputs (x0,x0+1)
    u64 p[27];
    #pragma unroll
    for (int c = 0; c < 3; c++) {
        float in[3][4];
        #pragma unroll
        for (int ky = 0; ky < 3; ky++) {
            int gy = y - 1 + ky;
            #pragma unroll
            for (int kx = 0; kx < 4; kx++) {
                int gx = x0 - 1 + kx;
                float v = 0.0f;
                if ((unsigned)gy < Hn && (unsigned)gx < Wn)
                    v = __ldg(chp[c] + gy * Wn + gx);
                in[ky][kx] = v;
            }
        }
        #pragma unroll
        for (int ky = 0; ky < 3; ky++)
            #pragma unroll
            for (int kx = 0; kx < 3; kx++)
                p[c * 9 + ky * 3 + kx] = pack2(in[ky][kx], in[ky][kx + 1]);
    }

    const u64* cw = (const u64*)c_w1d;
    #pragma unroll
    for (int oc = 0; oc < C1; oc++) {
        float bb = c_b1[oc];
        u64 acc = pack2(bb, bb);
        #pragma unroll
        for (int j = 0; j < 27; j++)
            fma2(acc, cw[oc * 27 + j], p[j]);
        float a0, a1;
        unpack2(acc, a0, a1);
        a0 = gelu_as(a0);
        a1 = gelu_as(a1);
        float2 o = make_float2(a0, a1);
        *(float2*)(g_feat + (((size_t)b * C1 + oc) * Hn + y) * Wn + x0) = o;
    }
}

// ---------------------------------------------------------------------------
// Bilinear sampling helpers
// ---------------------------------------------------------------------------
__device__ __forceinline__ float samp_point(const float* __restrict__ img,
                                            int yi, int xi) {
    bool valid = (yi >= 0) & (yi < Hn) & (xi >= 0) & (xi < Wn);
    int yc = min(max(yi, 0), Hn - 1);
    int xc = min(max(xi, 0), Wn - 1);
    float v = __ldg(img + yc * Wn + xc);
    return valid ? v : 0.0f;
}

__device__ __forceinline__ float bilinear(const float* __restrict__ img,
                                          float py, float px) {
    float fy = floorf(py), fx = floorf(px);
    float wy = py - fy,    wx = px - fx;
    int yi = (int)fy,      xi = (int)fx;
    float v00 = samp_point(img, yi,     xi);
    float v01 = samp_point(img, yi,     xi + 1);
    float v10 = samp_point(img, yi + 1, xi);
    float v11 = samp_point(img, yi + 1, xi + 1);
    float omy = 1.0f - wy, omx = 1.0f - wx;
    return v00 * omy * omx + v01 * omy * wx + v10 * wy * omx + v11 * wy * wx;
}

// ---------------------------------------------------------------------------
// Kernel 2 (unchanged): fused active-k conv2 + sampling.
// ---------------------------------------------------------------------------
__global__ __launch_bounds__(256, 4) void conv2_sample_kernel(
        const float* __restrict__ pm25,
        float* __restrict__ out) {
    extern __shared__ float sfeat[];                 // C1 * CPLANE floats

    int tid = threadIdx.x;                           // 256
    int bx0 = blockIdx.x * TW;
    int by0 = blockIdx.y * THY;
    int b   = blockIdx.z;

    {
        unsigned sbase = (unsigned)__cvta_generic_to_shared(sfeat);
        const float* src0 = g_feat + (size_t)b * C1 * Hn * Wn;
        #pragma unroll
        for (int m = 0; m < 12; m++) {
            int idx = tid + m * 256;
            if (idx < NCHUNK) {
                int j  = idx % 10;
                int rc = idx / 10;
                int yy = rc % HY;
                int c  = rc / HY;
                int gy  = by0 + yy - 1;
                int gx0 = bx0 - 4 + 4 * j;
                bool ok = ((unsigned)gy < Hn) & ((unsigned)gx0 < Wn);
                int gyc = min(max(gy, 0), Hn - 1);
                int gxc = ok ? gx0 : 0;
                cp_async16(sbase + (unsigned)((c * CPLANE + yy * W2R + 4 * j) * 4),
                           src0 + (size_t)c * Hn * Wn + (size_t)gyc * Wn + gxc, ok);
            }
        }
        asm volatile("cp.async.commit_group;" ::: "memory");
        asm volatile("cp.async.wait_group 0;" ::: "memory");
    }
    __syncthreads();

    int tx  = tid & 31;
    int r   = tid >> 5;
    int ylo = 2 * r;

    const float* img = pm25 + (size_t)b * Hn * Wn;
    int x = bx0 + tx;
    float ybase = (float)(by0 + ylo);
    float xf = (float)x;

    float o0 = 0.0f, o1 = 0.0f;

    #pragma unroll 1
    for (int k = 0; k < 9; k++) {
        float wkv = c_wk[k];
        if (wkv == 0.0f) continue;
        int oc0 = 2 * k;
        int oc1 = 2 * k + 1;

        float aY0 = c_b2[oc0], aY1 = aY0;
        float aX0 = c_b2[oc1], aX1 = aX0;

        #pragma unroll 4
        for (int c = 0; c < C1; c++) {
            const float* fp = sfeat + c * CPLANE + ylo * W2R + tx + 3;
            float fl[4][3];
            #pragma unroll
            for (int dy = 0; dy < 4; dy++)
                #pragma unroll
                for (int dx = 0; dx < 3; dx++)
                    fl[dy][dx] = fp[dy * W2R + dx];

            const float* wY = c_w2 + (oc0 * C1 + c) * 9;
            const float* wX = c_w2 + (oc1 * C1 + c) * 9;
            #pragma unroll
            for (int ky = 0; ky < 3; ky++)
                #pragma unroll
                for (int kx = 0; kx < 3; kx++) {
                    int t = ky * 3 + kx;
                    float vy = wY[t], vx = wX[t];
                    aY0 = fmaf(vy, fl[ky][kx],     aY0);
                    aY1 = fmaf(vy, fl[ky + 1][kx], aY1);
                    aX0 = fmaf(vx, fl[ky][kx],     aX0);
                    aX1 = fmaf(vx, fl[ky + 1][kx], aX1);
                }
        }

        float kdy = (float)(k / 3 - 1);
        float kdx = (float)(k % 3 - 1);
        o0 = fmaf(wkv, bilinear(img, ybase + 0.0f + kdy + aY0, xf + kdx + aX0), o0);
        o1 = fmaf(wkv, bilinear(img, ybase + 1.0f + kdy + aY1, xf + kdx + aX1), o1);
    }

    size_t ob = ((size_t)b * Hn + (by0 + ylo)) * Wn + x;
    out[ob]      = o0;
    out[ob + Wn] = o1;
}

// ---------------------------------------------------------------------------
extern "C" void kernel_launch(void* const* d_in, const int* in_sizes, int n_in,
                              void* d_out, int out_size) {
    const float* pm25 = (const float*)d_in[0];
    const float* wind = (const float*)d_in[1];
    const float* topo = (const float*)d_in[2];
    const float* w1   = (const float*)d_in[3];
    const float* b1   = (const float*)d_in[4];
    const float* w2   = (const float*)d_in[5];
    const float* b2   = (const float*)d_in[6];
    const float* wk   = (const float*)d_in[7];
    float* out = (float*)d_out;

    // Duplicate conv1 weights on device, then stage into constant memory.
    prep_weights_kernel<<<1, 512>>>(w1);
    void* w1d_ptr = nullptr;
    cudaGetSymbolAddress(&w1d_ptr, g_w1d);
    cudaMemcpyToSymbolAsync(c_w1d, w1d_ptr, C1 * 27 * sizeof(float2), 0,
                            cudaMemcpyDeviceToDevice, 0);
    cudaMemcpyToSymbolAsync(c_b1, b1, C1 * sizeof(float), 0,
                            cudaMemcpyDeviceToDevice, 0);
    cudaMemcpyToSymbolAsync(c_w2, w2, C2 * C1 * 9 * sizeof(float), 0,
                            cudaMemcpyDeviceToDevice, 0);
    cudaMemcpyToSymbolAsync(c_b2, b2, C2 * sizeof(float), 0,
                            cudaMemcpyDeviceToDevice, 0);
    cudaMemcpyToSymbolAsync(c_wk, wk, 9 * sizeof(float), 0,
                            cudaMemcpyDeviceToDevice, 0);

    // Kernel 1: conv1 + GELU (horizontal pairs, dup-const FFMA2, A-S gelu)
    int n1 = Bn * Hn * (Wn / 2);                  // 2,097,152 threads
    conv1_gelu_kernel<<<n1 / 256, 256>>>(wind, topo);

    // Kernel 2: fused active-k conv2 + sampling
    int smemB = C1 * CPLANE * (int)sizeof(float);    // 46080 B
    cudaFuncSetAttribute(conv2_sample_kernel,
                         cudaFuncAttributeMaxDynamicSharedMemorySize, smemB);
    dim3 grid(Wn / TW, Hn / THY, Bn);
    conv2_sample_kernel<<<grid, 256, smemB>>>(pm25, out);
}